// round 7
// baseline (speedup 1.0000x reference)
#include <cuda_runtime.h>
#include <cuda_bf16.h>

#define PADW 68   // 68 floats per row: 16B-aligned rows, conflict-managed banks

typedef unsigned long long u64;

// ---- packed f32x2 helpers (sm_103a FFMA2) ----
__device__ __forceinline__ u64 ffma2(u64 a, u64 b, u64 c){
    u64 d; asm("fma.rn.f32x2 %0, %1, %2, %3;" : "=l"(d) : "l"(a), "l"(b), "l"(c)); return d;
}
__device__ __forceinline__ u64 fadd2(u64 a, u64 b){
    u64 d; asm("add.rn.f32x2 %0, %1, %2;" : "=l"(d) : "l"(a), "l"(b)); return d;
}
__device__ __forceinline__ u64 fmul2(u64 a, u64 b){
    u64 d; asm("mul.rn.f32x2 %0, %1, %2;" : "=l"(d) : "l"(a), "l"(b)); return d;
}
__device__ __forceinline__ u64 dup2(float x){
    u64 d; asm("mov.b64 %0, {%1, %1};" : "=l"(d) : "f"(x)); return d;
}
__device__ __forceinline__ float hadd2(u64 a){
    float lo, hi; asm("mov.b64 {%0, %1}, %2;" : "=f"(lo), "=f"(hi) : "l"(a)); return lo + hi;
}

// scratch: per-chunk SSD states + wkv output (decoupled from 'out')
__device__ float g_states[2*16*32*64*64];
__device__ float g_y[2*2048*16*64];

// ---------------------------------------------------------------------------
// SSD chunk body (identical math to R2's passing kernel), as device function.
// ---------------------------------------------------------------------------
__device__ void ssd_chunk_body(int blk, float* sm,
    const float* __restrict__ Xg, const float* __restrict__ Ag,
    const float* __restrict__ Bg, const float* __restrict__ Cg,
    float* __restrict__ out)
{
    float* sC   = sm;
    float* sB   = sC + 64*PADW;
    float* sX   = sB + 64*PADW;
    float* sG   = sX + 64*PADW;
    float* sCum = sG + 64*PADW;   // 64
    float* sDec = sCum + 64;      // 64

    int c  = blk & 31;
    int bh = blk >> 5;
    int b  = bh >> 4, h = bh & 15;
    int tid = threadIdx.x;

    long long gbase = ((long long)b*2048 + c*64)*1024 + h*64;

    for (int e = tid; e < 4096; e += 256){
        int l = e >> 6, p = e & 63;
        long long gi = gbase + (long long)l*1024 + p;
        int si = l*PADW + p;
        sC[si] = Cg[gi];
        sB[si] = Bg[gi];
        sX[si] = Xg[gi];
    }
    if (tid < 64) sCum[tid] = Ag[((long long)b*2048 + c*64 + tid)*16 + h];
    __syncthreads();
    if (tid == 0){
        float run = 0.f;
        for (int l = 0; l < 64; l++){ run += sCum[l]; sCum[l] = run; }
    }
    __syncthreads();
    if (tid < 64) sDec[tid] = expf(sCum[63] - sCum[tid]);

    int l  = tid >> 2;
    int pg = tid & 3;

    // ---- pass 1: G[l][s] ----
    float g[16];
#pragma unroll
    for (int i = 0; i < 16; i++) g[i] = 0.f;
    {
        const float4* c4 = (const float4*)(sC + l*PADW);
#pragma unroll 4
        for (int n4 = 0; n4 < 16; n4++){
            float4 cv = c4[n4];
#pragma unroll
            for (int si = 0; si < 16; si++){
                int s = 4*si + pg;
                float4 bv = ((const float4*)(sB + s*PADW))[n4];
                g[si] += cv.x*bv.x + cv.y*bv.y + cv.z*bv.z + cv.w*bv.w;
            }
        }
    }
    float cuml = sCum[l];
#pragma unroll
    for (int si = 0; si < 16; si++){
        int s = 4*si + pg;
        sG[l*PADW + s] = (s <= l) ? g[si]*expf(cuml - sCum[s]) : 0.f;
    }
    __syncthreads();

    // ---- pass 2: Y_diag ----
    float acc[16];
#pragma unroll
    for (int i = 0; i < 16; i++) acc[i] = 0.f;
    for (int s = 0; s < 64; s++){
        float gv = sG[l*PADW + s];
        const float4* x4 = (const float4*)(sX + s*PADW) + pg*4;
#pragma unroll
        for (int q4 = 0; q4 < 4; q4++){
            float4 xv = x4[q4];
            acc[q4*4+0] += gv*xv.x;
            acc[q4*4+1] += gv*xv.y;
            acc[q4*4+2] += gv*xv.z;
            acc[q4*4+3] += gv*xv.w;
        }
    }
    {
        float4* op = (float4*)(out + gbase + (long long)l*1024 + pg*16);
#pragma unroll
        for (int q4 = 0; q4 < 4; q4++){
            float4 ov;
            ov.x = acc[q4*4+0]; ov.y = acc[q4*4+1];
            ov.z = acc[q4*4+2]; ov.w = acc[q4*4+3];
            op[q4] = ov;
        }
    }

    // ---- pass 3: states ----
    int pp = tid >> 2, ng = tid & 3;
#pragma unroll
    for (int i = 0; i < 16; i++) acc[i] = 0.f;
    for (int l2 = 0; l2 < 64; l2++){
        float t = sDec[l2] * sX[l2*PADW + pp];
        const float4* b4 = (const float4*)(sB + l2*PADW) + ng*4;
#pragma unroll
        for (int q4 = 0; q4 < 4; q4++){
            float4 bv = b4[q4];
            acc[q4*4+0] += t*bv.x;
            acc[q4*4+1] += t*bv.y;
            acc[q4*4+2] += t*bv.z;
            acc[q4*4+3] += t*bv.w;
        }
    }
    {
        float4* sp = (float4*)(g_states + ((long long)bh*32 + c)*4096 + pp*64 + ng*16);
#pragma unroll
        for (int q4 = 0; q4 < 4; q4++){
            float4 sv;
            sv.x = acc[q4*4+0]; sv.y = acc[q4*4+1];
            sv.z = acc[q4*4+2]; sv.w = acc[q4*4+3];
            sp[q4] = sv;
        }
    }
}

// ---------------------------------------------------------------------------
// WKV v3 step: three dots from start-of-step data, one parallel reduce,
// rescaled state Shat = S / P (P = running prod(w) per row, reset per tile).
//   d1 = delta_t . k_t          (output term)
//   d2 = delta_t . k_{t+1}
//   d3 = Shat_{t-1} . k_{t+1}
//   sk_{t+1}[i] = P_t[i]*d3 + bk_t[i]*d2 ;  delta_{t+1} = v_{t+1} - sk_{t+1}
//   y_t[i] = r_t[i]*( w_t[i]*(v_t[i]-delta_t[i]) + bk_t[i]*d1 )
//   Shat_t = Shat_{t-1} + (bk_t/P_t) * delta_t
// ---------------------------------------------------------------------------
#define WTILE 32
#define SLOT  320    // k(64) v(64) w(64) b(64) r(64)

__device__ __forceinline__ void wkv_step(
    const float* __restrict__ stp,        // tile slot for step t (holds step t+1 data)
    const float* __restrict__ dsrc,       // delta_t buffer
    float* __restrict__ ddst,             // delta_{t+1} buffer
    float* __restrict__ gyrow,            // g_y + obase + t*1024
    u64 (&kcur)[8], u64 (&knxt)[8], u64 (&S)[8],
    float& wi, float& rwi, float& bki, float& ri, float& vi, float& di,
    float& Pi, float& PiInv, int i, int q, int j0)
{
    // delta_t slice
    u64 d2r[8];
    {
        const ulonglong2* dp = (const ulonglong2*)(dsrc + j0);
        ulonglong2 t0 = dp[0], t1 = dp[1], t2 = dp[2], t3 = dp[3];
        d2r[0]=t0.x; d2r[1]=t0.y; d2r[2]=t1.x; d2r[3]=t1.y;
        d2r[4]=t2.x; d2r[5]=t2.y; d2r[6]=t3.x; d2r[7]=t3.y;
    }
    // k_{t+1} slice
    {
        const ulonglong2* kp = (const ulonglong2*)(stp + j0);
        ulonglong2 t0 = kp[0], t1 = kp[1], t2 = kp[2], t3 = kp[3];
        knxt[0]=t0.x; knxt[1]=t0.y; knxt[2]=t1.x; knxt[3]=t1.y;
        knxt[4]=t2.x; knxt[5]=t2.y; knxt[6]=t3.x; knxt[7]=t3.y;
    }
    // next-step per-row scalars
    float wn = stp[128 + i];
    float bn = stp[192 + i] * stp[i];
    float rn = stp[256 + i];
    float vn = stp[64 + i];

    // three dots
    u64 a0=0ull, a1=0ull, b0=0ull, b1=0ull, c0=0ull, c1=0ull;
#pragma unroll
    for (int m = 0; m < 8; m += 2){
        a0 = ffma2(d2r[m],   kcur[m],   a0);
        a1 = ffma2(d2r[m+1], kcur[m+1], a1);
        b0 = ffma2(d2r[m],   knxt[m],   b0);
        b1 = ffma2(d2r[m+1], knxt[m+1], b1);
        c0 = ffma2(S[m],     knxt[m],   c0);
        c1 = ffma2(S[m+1],   knxt[m+1], c1);
    }
    float d1  = hadd2(fadd2(a0, a1));
    float dd2 = hadd2(fadd2(b0, b1));
    float dd3 = hadd2(fadd2(c0, c1));
    // one parallel 2-level reduce for all three
    d1  += __shfl_xor_sync(0xffffffffu, d1, 1);
    dd2 += __shfl_xor_sync(0xffffffffu, dd2, 1);
    dd3 += __shfl_xor_sync(0xffffffffu, dd3, 1);
    d1  += __shfl_xor_sync(0xffffffffu, d1, 2);
    dd2 += __shfl_xor_sync(0xffffffffu, dd2, 2);
    dd3 += __shfl_xor_sync(0xffffffffu, dd3, 2);

    float Pn    = Pi * wi;
    float PnInv = PiInv * rwi;
    float skn   = Pn*dd3 + bki*dd2;
    float dn    = vn - skn;
    if (q == 0){
        ddst[i]  = dn;
        gyrow[i] = ri * (wi*(vi - di) + bki*d1);
    }
    // state update (off the serial chain until next step's d3)
    u64 cb = dup2(bki * PnInv);
#pragma unroll
    for (int m = 0; m < 8; m++) S[m] = ffma2(cb, d2r[m], S[m]);

    // rotate scalars
    wi = wn; rwi = __fdividef(1.f, wn); bki = bn; ri = rn; vi = vn; di = dn;
    Pi = Pn; PiInv = PnInv;
    __syncthreads();
}

__device__ void wkv_body(float* sh,
    const float* __restrict__ rg, const float* __restrict__ kg,
    const float* __restrict__ vg, const float* __restrict__ wg,
    const float* __restrict__ bg)
{
    float* dsp = sh + 2*WTILE*SLOT;   // [2][64] delta double buffer

    int bw = blockIdx.x;
    int bq = bw >> 4, h = bw & 15;
    int tid = threadIdx.x, i = tid >> 2, q = tid & 3, j0 = q * 16;
    long long base  = (long long)bw * 2048 * 64;
    long long obase = (long long)bq * 2048 * 1024 + h * 64;

    const float* kb = kg + base;
    const float* vb = vg + base;
    const float* wb = wg + base;
    const float* bb = bg + base;
    const float* rb = rg + base;

    // tile staging: buffer n holds steps 32n+1 .. 32n+32 (clamped)
    auto stage = [&](int n, float* dst){
#pragma unroll 1
        for (int c = tid; c < 5*512; c += 256){
            int a = c >> 9, rem = c & 511, t = rem >> 4, off = (rem & 15) << 2;
            int s = 32*n + 1 + t; if (s > 2047) s = 2047;
            const float* src;
            long long so = (long long)s*64 + off;
            if      (a == 0) src = kb + so;
            else if (a == 1) src = vb + so;
            else if (a == 2) src = wb + so;
            else if (a == 3) src = bb + so;
            else             src = rb + so;
            unsigned du = (unsigned)__cvta_generic_to_shared(dst + (t*5 + a)*64 + off);
            asm volatile("cp.async.cg.shared.global [%0], [%1], 16;" :: "r"(du), "l"(src));
        }
        asm volatile("cp.async.commit_group;" ::: "memory");
    };

    u64 S[8];
#pragma unroll
    for (int m = 0; m < 8; m++) S[m] = 0ull;

    stage(0, sh);

    // prologue: step-0 data from global
    u64 kkA[8], kkB[8];
    {
        const ulonglong2* kp = (const ulonglong2*)(kb + j0);
        ulonglong2 t0 = kp[0], t1 = kp[1], t2 = kp[2], t3 = kp[3];
        kkA[0]=t0.x; kkA[1]=t0.y; kkA[2]=t1.x; kkA[3]=t1.y;
        kkA[4]=t2.x; kkA[5]=t2.y; kkA[6]=t3.x; kkA[7]=t3.y;
    }
    float wi  = wb[i];
    float rwi = __fdividef(1.f, wi);
    float bki = bb[i] * kb[i];
    float ri  = rb[i];
    float vi  = vb[i];
    float di  = vi;                 // delta_0 = v_0 (S=0)
    float Pi  = 1.f, PiInv = 1.f;
    if (q == 0) dsp[i] = vi;        // publish delta_0 (parity 0)

    float* gyb = g_y + obase;

    for (int n = 0; n < 64; n++){
        float* buf = sh + (n & 1)*WTILE*SLOT;
        if (n < 63){
            stage(n + 1, sh + ((n + 1) & 1)*WTILE*SLOT);
            asm volatile("cp.async.wait_group 1;" ::: "memory");
        } else {
            asm volatile("cp.async.wait_group 0;" ::: "memory");
        }
        __syncthreads();

        float* gyr = gyb + (long long)(n*32)*1024;
#pragma unroll 2
        for (int tt = 0; tt < WTILE; tt += 2){
            wkv_step(buf + tt*SLOT,       dsp,      dsp + 64, gyr,
                     kkA, kkB, S, wi, rwi, bki, ri, vi, di, Pi, PiInv, i, q, j0);
            gyr += 1024;
            wkv_step(buf + (tt + 1)*SLOT, dsp + 64, dsp,      gyr,
                     kkB, kkA, S, wi, rwi, bki, ri, vi, di, Pi, PiInv, i, q, j0);
            gyr += 1024;
        }
        // rescale state to the true S at tile end; reset P
        u64 pp = dup2(Pi);
#pragma unroll
        for (int m = 0; m < 8; m++) S[m] = fmul2(S[m], pp);
        Pi = 1.f; PiInv = 1.f;
    }
}

// ---------------------------------------------------------------------------
// Fused kernel: bid 0..31 -> wkv (latency-critical, isolated SMs via 120KB smem);
//               bid 32..1055 -> ssd chunk work on the remaining SMs.
// ---------------------------------------------------------------------------
__global__ __launch_bounds__(256) void fused_kernel(
    const float* __restrict__ Xg, const float* __restrict__ Ag,
    const float* __restrict__ Bg, const float* __restrict__ Cg,
    const float* __restrict__ rg, const float* __restrict__ kg,
    const float* __restrict__ vg, const float* __restrict__ wg,
    const float* __restrict__ bg, float* __restrict__ out)
{
    extern __shared__ float sm[];
    if (blockIdx.x < 32) wkv_body(sm, rg, kg, vg, wg, bg);
    else                 ssd_chunk_body(blockIdx.x - 32, sm, Xg, Ag, Bg, Cg, out);
}

// ---------------------------------------------------------------------------
// Kernel B: cross-chunk state scan (unchanged). grid=32, 256t.
// ---------------------------------------------------------------------------
__global__ __launch_bounds__(256) void ssd_state_scan_kernel(const float* __restrict__ Ag)
{
    int bh = blockIdx.x;
    int b = bh >> 4, h = bh & 15;
    __shared__ float atot[32];
    int tid = threadIdx.x;
    if (tid < 32){
        float s = 0.f;
        long long base = ((long long)b*2048 + tid*64)*16 + h;
        for (int l = 0; l < 64; l++) s += Ag[base + (long long)l*16];
        atot[tid] = s;
    }
    __syncthreads();
    float S[16];
#pragma unroll
    for (int i = 0; i < 16; i++) S[i] = 0.f;
    float* base = g_states + (long long)bh*32*4096;
    for (int c = 0; c < 32; c++){
        float dec = expf(atot[c]);
        float* p = base + (long long)c*4096;
#pragma unroll
        for (int r2 = 0; r2 < 16; r2++){
            int e = r2*256 + tid;
            float st = p[e];
            p[e] = S[r2];
            S[r2] = S[r2]*dec + st;
        }
    }
}

// ---------------------------------------------------------------------------
// Kernel C: Y_off + final g_y add. grid=1024, 256t.
// out = Y_diag (already there) + Y_off + g_y
// ---------------------------------------------------------------------------
__global__ __launch_bounds__(256) void ssd_yoff_kernel(
    const float* __restrict__ Ag, const float* __restrict__ Cg,
    float* __restrict__ out)
{
    __shared__ float sC[64*PADW];
    __shared__ float sS[64*PADW];
    __shared__ float sCum[64];
    int blk = blockIdx.x;
    int c  = blk & 31;
    int bh = blk >> 5;
    int b  = bh >> 4, h = bh & 15;
    int tid = threadIdx.x;
    long long gbase = ((long long)b*2048 + c*64)*1024 + h*64;
    const float* st = g_states + ((long long)bh*32 + c)*4096;

    for (int e = tid; e < 4096; e += 256){
        int l = e >> 6, p = e & 63;       // here l == pp, p == n
        sC[l*PADW + p] = Cg[gbase + (long long)l*1024 + p];
        sS[p*PADW + l] = st[(l << 6) | p];   // transposed: sS[n][pp]
    }
    if (tid < 64) sCum[tid] = Ag[((long long)b*2048 + c*64 + tid)*16 + h];
    __syncthreads();
    if (tid == 0){
        float run = 0.f;
        for (int l = 0; l < 64; l++){ run += sCum[l]; sCum[l] = run; }
    }
    __syncthreads();

    int l  = tid >> 2;
    int pg = tid & 3;
    float acc[16];
#pragma unroll
    for (int i = 0; i < 16; i++) acc[i] = 0.f;
    for (int n = 0; n < 64; n++){
        float cv = sC[l*PADW + n];
        const float4* s4 = (const float4*)(sS + n*PADW) + pg*4;
#pragma unroll
        for (int q4 = 0; q4 < 4; q4++){
            float4 sv = s4[q4];
            acc[q4*4+0] += cv*sv.x;
            acc[q4*4+1] += cv*sv.y;
            acc[q4*4+2] += cv*sv.z;
            acc[q4*4+3] += cv*sv.w;
        }
    }
    float d = expf(sCum[l]);
    float4* op = (float4*)(out + gbase + (long long)l*1024 + pg*16);
    const float4* gp = (const float4*)(g_y + gbase + (long long)l*1024 + pg*16);
#pragma unroll
    for (int q4 = 0; q4 < 4; q4++){
        float4 ov = op[q4];
        float4 gv = gp[q4];
        ov.x += d*acc[q4*4+0] + gv.x;
        ov.y += d*acc[q4*4+1] + gv.y;
        ov.z += d*acc[q4*4+2] + gv.z;
        ov.w += d*acc[q4*4+3] + gv.w;
        op[q4] = ov;
    }
}

// ---------------------------------------------------------------------------
extern "C" void kernel_launch(void* const* d_in, const int* in_sizes, int n_in,
                              void* d_out, int out_size)
{
    const float* X  = (const float*)d_in[0];
    const float* A  = (const float*)d_in[1];
    const float* B  = (const float*)d_in[2];
    const float* C  = (const float*)d_in[3];
    const float* r  = (const float*)d_in[4];
    const float* k  = (const float*)d_in[5];
    const float* v  = (const float*)d_in[6];
    const float* w  = (const float*)d_in[7];
    const float* bn = (const float*)d_in[8];
    float* out = (float*)d_out;

    // 120 KB dynamic smem: forces 1 block/SM so the 32 latency-critical wkv
    // blocks never share an SM with ssd FFMA blocks. (wkv needs ~81KB, ssd ~70KB)
    const size_t smemF = 120 * 1024;
    cudaFuncSetAttribute(fused_kernel,
                         cudaFuncAttributeMaxDynamicSharedMemorySize, (int)smemF);

    fused_kernel<<<32 + 1024, 256, smemF>>>(X, A, B, C, r, k, v, w, bn, out);
    ssd_state_scan_kernel<<<32, 256>>>(A);
    ssd_yoff_kernel<<<1024, 256>>>(A, C, out);
}

// round 9
// speedup vs baseline: 1.1722x; 1.1722x over previous
#include <cuda_runtime.h>
#include <cuda_bf16.h>

#define PADW 68   // 68 floats per row: 16B-aligned rows, conflict-managed banks

typedef unsigned long long u64;

// ---- packed f32x2 helpers (sm_103a FFMA2) ----
__device__ __forceinline__ u64 ffma2(u64 a, u64 b, u64 c){
    u64 d; asm("fma.rn.f32x2 %0, %1, %2, %3;" : "=l"(d) : "l"(a), "l"(b), "l"(c)); return d;
}
__device__ __forceinline__ u64 fmul2(u64 a, u64 b){
    u64 d; asm("mul.rn.f32x2 %0, %1, %2;" : "=l"(d) : "l"(a), "l"(b)); return d;
}
__device__ __forceinline__ u64 dup2(float x){
    u64 d; asm("mov.b64 %0, {%1, %1};" : "=l"(d) : "f"(x)); return d;
}
__device__ __forceinline__ float hadd2(u64 a){
    float lo, hi; asm("mov.b64 {%0, %1}, %2;" : "=f"(lo), "=f"(hi) : "l"(a)); return lo + hi;
}

// scratch: per-chunk SSD states + wkv output (decoupled from 'out')
__device__ float g_states[2*16*32*64*64];
__device__ float g_y[2*2048*16*64];

// ---------------------------------------------------------------------------
// SSD chunk body (R1/R2 math, unchanged). 256 threads.
// ---------------------------------------------------------------------------
__device__ void ssd_chunk_body(int blk, float* sm,
    const float* __restrict__ Xg, const float* __restrict__ Ag,
    const float* __restrict__ Bg, const float* __restrict__ Cg,
    float* __restrict__ out)
{
    float* sC   = sm;
    float* sB   = sC + 64*PADW;
    float* sX   = sB + 64*PADW;
    float* sG   = sX + 64*PADW;
    float* sCum = sG + 64*PADW;   // 64
    float* sDec = sCum + 64;      // 64

    int c  = blk & 31;
    int bh = blk >> 5;
    int b  = bh >> 4, h = bh & 15;
    int tid = threadIdx.x;

    long long gbase = ((long long)b*2048 + c*64)*1024 + h*64;

    for (int e = tid; e < 4096; e += 256){
        int l = e >> 6, p = e & 63;
        long long gi = gbase + (long long)l*1024 + p;
        int si = l*PADW + p;
        sC[si] = Cg[gi];
        sB[si] = Bg[gi];
        sX[si] = Xg[gi];
    }
    if (tid < 64) sCum[tid] = Ag[((long long)b*2048 + c*64 + tid)*16 + h];
    __syncthreads();
    if (tid == 0){
        float run = 0.f;
        for (int l = 0; l < 64; l++){ run += sCum[l]; sCum[l] = run; }
    }
    __syncthreads();
    if (tid < 64) sDec[tid] = expf(sCum[63] - sCum[tid]);

    int l  = tid >> 2;
    int pg = tid & 3;

    // ---- pass 1: G[l][s] ----
    float g[16];
#pragma unroll
    for (int i = 0; i < 16; i++) g[i] = 0.f;
    {
        const float4* c4 = (const float4*)(sC + l*PADW);
#pragma unroll 4
        for (int n4 = 0; n4 < 16; n4++){
            float4 cv = c4[n4];
#pragma unroll
            for (int si = 0; si < 16; si++){
                int s = 4*si + pg;
                float4 bv = ((const float4*)(sB + s*PADW))[n4];
                g[si] += cv.x*bv.x + cv.y*bv.y + cv.z*bv.z + cv.w*bv.w;
            }
        }
    }
    float cuml = sCum[l];
#pragma unroll
    for (int si = 0; si < 16; si++){
        int s = 4*si + pg;
        sG[l*PADW + s] = (s <= l) ? g[si]*expf(cuml - sCum[s]) : 0.f;
    }
    __syncthreads();

    // ---- pass 2: Y_diag ----
    float acc[16];
#pragma unroll
    for (int i = 0; i < 16; i++) acc[i] = 0.f;
    for (int s = 0; s < 64; s++){
        float gv = sG[l*PADW + s];
        const float4* x4 = (const float4*)(sX + s*PADW) + pg*4;
#pragma unroll
        for (int q4 = 0; q4 < 4; q4++){
            float4 xv = x4[q4];
            acc[q4*4+0] += gv*xv.x;
            acc[q4*4+1] += gv*xv.y;
            acc[q4*4+2] += gv*xv.z;
            acc[q4*4+3] += gv*xv.w;
        }
    }
    {
        float4* op = (float4*)(out + gbase + (long long)l*1024 + pg*16);
#pragma unroll
        for (int q4 = 0; q4 < 4; q4++){
            float4 ov;
            ov.x = acc[q4*4+0]; ov.y = acc[q4*4+1];
            ov.z = acc[q4*4+2]; ov.w = acc[q4*4+3];
            op[q4] = ov;
        }
    }

    // ---- pass 3: states ----
    int pp = tid >> 2, ng = tid & 3;
#pragma unroll
    for (int i = 0; i < 16; i++) acc[i] = 0.f;
    for (int l2 = 0; l2 < 64; l2++){
        float t = sDec[l2] * sX[l2*PADW + pp];
        const float4* b4 = (const float4*)(sB + l2*PADW) + ng*4;
#pragma unroll
        for (int q4 = 0; q4 < 4; q4++){
            float4 bv = b4[q4];
            acc[q4*4+0] += t*bv.x;
            acc[q4*4+1] += t*bv.y;
            acc[q4*4+2] += t*bv.z;
            acc[q4*4+3] += t*bv.w;
        }
    }
    {
        float4* sp = (float4*)(g_states + ((long long)bh*32 + c)*4096 + pp*64 + ng*16);
#pragma unroll
        for (int q4 = 0; q4 < 4; q4++){
            float4 sv;
            sv.x = acc[q4*4+0]; sv.y = acc[q4*4+1];
            sv.z = acc[q4*4+2]; sv.w = acc[q4*4+3];
            sp[q4] = sv;
        }
    }
}

// ---------------------------------------------------------------------------
// WKV body — EXACT v2 step (R2's 749us version), writing y to g_y instead of
// accumulating into out (5 staged arrays, no out prefetch).
// Thread (i = tid>>2 row, q = tid&3 -> 16 cols). One barrier per step.
//   A phase: dkk = delta_t . k_t ; y_t = r*(w*sk + bk*dkk) ; S += update
//   B phase: sk = S_t . k_{t+1} ; delta_{t+1} = v_{t+1} - sk
// ---------------------------------------------------------------------------
#define WTILE 32
#define SLOT  320    // k(64) v(64) w(64) b(64) r(64)

__device__ void wkv_body(float* sh,
    const float* __restrict__ rg, const float* __restrict__ kg,
    const float* __restrict__ vg, const float* __restrict__ wg,
    const float* __restrict__ bg)
{
    float* dsp = sh + 2*WTILE*SLOT;   // [2][64] delta double buffer

    int bw = blockIdx.x;
    int bq = bw >> 4, h = bw & 15;
    int tid = threadIdx.x, i = tid >> 2, q = tid & 3, j0 = q * 16;
    long long base  = (long long)bw * 2048 * 64;
    long long obase = (long long)bq * 2048 * 1024 + h * 64;

    const float* kb = kg + base;
    const float* vb = vg + base;
    const float* wb = wg + base;
    const float* bb = bg + base;
    const float* rb = rg + base;
    float* gyb = g_y + obase;

    // tile staging: buffer n holds steps 32n+1 .. 32n+32 (clamped)
    auto stage = [&](int n, float* dst){
#pragma unroll 1
        for (int c = tid; c < 5*512; c += 256){
            int a = c >> 9, rem = c & 511, t = rem >> 4, off = (rem & 15) << 2;
            int s = 32*n + 1 + t; if (s > 2047) s = 2047;
            const float* src;
            long long so = (long long)s*64 + off;
            if      (a == 0) src = kb + so;
            else if (a == 1) src = vb + so;
            else if (a == 2) src = wb + so;
            else if (a == 3) src = bb + so;
            else             src = rb + so;
            unsigned du = (unsigned)__cvta_generic_to_shared(dst + (t*5 + a)*64 + off);
            asm volatile("cp.async.cg.shared.global [%0], [%1], 16;" :: "r"(du), "l"(src));
        }
        asm volatile("cp.async.commit_group;" ::: "memory");
    };

    u64 S[8];
#pragma unroll
    for (int m = 0; m < 8; m++) S[m] = 0ull;

    stage(0, sh);                     // buffer 0 <- steps 1..32

    // prologue: step-0 data straight from global
    u64 kj[8];
    {
        const ulonglong2* kp = (const ulonglong2*)(kb + j0);
#pragma unroll
        for (int m = 0; m < 4; m++){ ulonglong2 t2 = kp[m]; kj[2*m] = t2.x; kj[2*m+1] = t2.y; }
    }
    float wi  = wb[i];
    float bki = bb[i] * kb[i];
    float ri  = rb[i];
    if (q == 0) dsp[i] = vb[i];       // delta_0 = v_0 (S=0), parity 0
    float sk = 0.f;                   // S_{-1} . k_0 = 0

    for (int n = 0; n < 64; n++){
        float* buf = sh + (n & 1)*WTILE*SLOT;
        if (n < 63){
            stage(n + 1, sh + ((n + 1) & 1)*WTILE*SLOT);
            asm volatile("cp.async.wait_group 1;" ::: "memory");
        } else {
            asm volatile("cp.async.wait_group 0;" ::: "memory");
        }
        __syncthreads();

        float* gyr = gyb + (long long)(n*32)*1024;
#pragma unroll 4
        for (int tt = 0; tt < WTILE; tt++){
            int p = tt & 1;

            // ======== A: consume delta_t ========
            u64 d2[8];
            {
                const ulonglong2* dp = (const ulonglong2*)(dsp + p*64 + j0);
#pragma unroll
                for (int m = 0; m < 4; m++){ ulonglong2 t2 = dp[m]; d2[2*m] = t2.x; d2[2*m+1] = t2.y; }
            }
            u64 a0 = 0ull, a1 = 0ull;
#pragma unroll
            for (int m = 0; m < 8; m += 2){
                a0 = ffma2(d2[m],   kj[m],   a0);
                a1 = ffma2(d2[m+1], kj[m+1], a1);
            }
            float dkk = hadd2(a0) + hadd2(a1);
            dkk += __shfl_xor_sync(0xffffffffu, dkk, 1);
            dkk += __shfl_xor_sync(0xffffffffu, dkk, 2);

            if (q == 0){
                gyr[i] = ri * (wi*sk + bki*dkk);
            }

            u64 w2 = dup2(wi), bk2 = dup2(bki);
#pragma unroll
            for (int m = 0; m < 8; m++)
                S[m] = ffma2(S[m], w2, fmul2(bk2, d2[m]));

            // ======== B: produce delta_{t+1} from tile slot tt ========
            const float* stp = buf + tt*SLOT;
            {
                const ulonglong2* kp = (const ulonglong2*)(stp + j0);
#pragma unroll
                for (int m = 0; m < 4; m++){ ulonglong2 t2 = kp[m]; kj[2*m] = t2.x; kj[2*m+1] = t2.y; }
            }
            u64 b0 = 0ull, b1 = 0ull;
#pragma unroll
            for (int m = 0; m < 8; m += 2){
                b0 = ffma2(S[m],   kj[m],   b0);
                b1 = ffma2(S[m+1], kj[m+1], b1);
            }
            float skn = hadd2(b0) + hadd2(b1);
            skn += __shfl_xor_sync(0xffffffffu, skn, 1);
            skn += __shfl_xor_sync(0xffffffffu, skn, 2);

            wi  = stp[128 + i];
            bki = stp[192 + i] * stp[i];
            if (q == 0){
                ri = stp[256 + i];
                float vi = stp[64 + i];
                dsp[(p ^ 1)*64 + i] = vi - skn;
            }
            sk = skn;
            gyr += 1024;
            __syncthreads();
        }
    }
}

// ---------------------------------------------------------------------------
// Fused kernel: bid 0..31 -> wkv (isolated SMs via 120KB smem);
//               bid 32..1055 -> ssd chunk work on the remaining SMs.
// ---------------------------------------------------------------------------
__global__ __launch_bounds__(256) void fused_kernel(
    const float* __restrict__ Xg, const float* __restrict__ Ag,
    const float* __restrict__ Bg, const float* __restrict__ Cg,
    const float* __restrict__ rg, const float* __restrict__ kg,
    const float* __restrict__ vg, const float* __restrict__ wg,
    const float* __restrict__ bg, float* __restrict__ out)
{
    extern __shared__ float sm[];
    if (blockIdx.x < 32) wkv_body(sm, rg, kg, vg, wg, bg);
    else                 ssd_chunk_body(blockIdx.x - 32, sm, Xg, Ag, Bg, Cg, out);
}

// ---------------------------------------------------------------------------
// Kernel B: cross-chunk state scan. grid=32, 256t.
// ---------------------------------------------------------------------------
__global__ __launch_bounds__(256) void ssd_state_scan_kernel(const float* __restrict__ Ag)
{
    int bh = blockIdx.x;
    int b = bh >> 4, h = bh & 15;
    __shared__ float atot[32];
    int tid = threadIdx.x;
    if (tid < 32){
        float s = 0.f;
        long long base = ((long long)b*2048 + tid*64)*16 + h;
        for (int l = 0; l < 64; l++) s += Ag[base + (long long)l*16];
        atot[tid] = s;
    }
    __syncthreads();
    float S[16];
#pragma unroll
    for (int i = 0; i < 16; i++) S[i] = 0.f;
    float* base = g_states + (long long)bh*32*4096;
    for (int c = 0; c < 32; c++){
        float dec = expf(atot[c]);
        float* p = base + (long long)c*4096;
#pragma unroll
        for (int r2 = 0; r2 < 16; r2++){
            int e = r2*256 + tid;
            float st = p[e];
            p[e] = S[r2];
            S[r2] = S[r2]*dec + st;
        }
    }
}

// ---------------------------------------------------------------------------
// Kernel C: Y_off + final g_y add. grid=1024, 256t.
// out = Y_diag (already there) + Y_off + g_y
// ---------------------------------------------------------------------------
__global__ __launch_bounds__(256) void ssd_yoff_kernel(
    const float* __restrict__ Ag, const float* __restrict__ Cg,
    float* __restrict__ out)
{
    __shared__ float sC[64*PADW];
    __shared__ float sS[64*PADW];
    __shared__ float sCum[64];
    int blk = blockIdx.x;
    int c  = blk & 31;
    int bh = blk >> 5;
    int b  = bh >> 4, h = bh & 15;
    int tid = threadIdx.x;
    long long gbase = ((long long)b*2048 + c*64)*1024 + h*64;
    const float* st = g_states + ((long long)bh*32 + c)*4096;

    for (int e = tid; e < 4096; e += 256){
        int l = e >> 6, p = e & 63;       // here l == pp, p == n
        sC[l*PADW + p] = Cg[gbase + (long long)l*1024 + p];
        sS[p*PADW + l] = st[(l << 6) | p];   // transposed: sS[n][pp]
    }
    if (tid < 64) sCum[tid] = Ag[((long long)b*2048 + c*64 + tid)*16 + h];
    __syncthreads();
    if (tid == 0){
        float run = 0.f;
        for (int l = 0; l < 64; l++){ run += sCum[l]; sCum[l] = run; }
    }
    __syncthreads();

    int l  = tid >> 2;
    int pg = tid & 3;
    float acc[16];
#pragma unroll
    for (int i = 0; i < 16; i++) acc[i] = 0.f;
    for (int n = 0; n < 64; n++){
        float cv = sC[l*PADW + n];
        const float4* s4 = (const float4*)(sS + n*PADW) + pg*4;
#pragma unroll
        for (int q4 = 0; q4 < 4; q4++){
            float4 sv = s4[q4];
            acc[q4*4+0] += cv*sv.x;
            acc[q4*4+1] += cv*sv.y;
            acc[q4*4+2] += cv*sv.z;
            acc[q4*4+3] += cv*sv.w;
        }
    }
    float d = expf(sCum[l]);
    float4* op = (float4*)(out + gbase + (long long)l*1024 + pg*16);
    const float4* gp = (const float4*)(g_y + gbase + (long long)l*1024 + pg*16);
#pragma unroll
    for (int q4 = 0; q4 < 4; q4++){
        float4 ov = op[q4];
        float4 gv = gp[q4];
        ov.x += d*acc[q4*4+0] + gv.x;
        ov.y += d*acc[q4*4+1] + gv.y;
        ov.z += d*acc[q4*4+2] + gv.z;
        ov.w += d*acc[q4*4+3] + gv.w;
        op[q4] = ov;
    }
}

// ---------------------------------------------------------------------------
extern "C" void kernel_launch(void* const* d_in, const int* in_sizes, int n_in,
                              void* d_out, int out_size)
{
    const float* X  = (const float*)d_in[0];
    const float* A  = (const float*)d_in[1];
    const float* B  = (const float*)d_in[2];
    const float* C  = (const float*)d_in[3];
    const float* r  = (const float*)d_in[4];
    const float* k  = (const float*)d_in[5];
    const float* v  = (const float*)d_in[6];
    const float* w  = (const float*)d_in[7];
    const float* bn = (const float*)d_in[8];
    float* out = (float*)d_out;

    // 120 KB dynamic smem: 1 block/SM so the 32 latency-critical wkv blocks
    // never share an SM with ssd FFMA blocks. (wkv needs ~81KB, ssd ~70KB)
    const size_t smemF = 120 * 1024;
    cudaFuncSetAttribute(fused_kernel,
                         cudaFuncAttributeMaxDynamicSharedMemorySize, (int)smemF);

    fused_kernel<<<32 + 1024, 256, smemF>>>(X, A, B, C, r, k, v, w, bn, out);
    ssd_state_scan_kernel<<<32, 256>>>(A);
    ssd_yoff_kernel<<<1024, 256>>>(A, C, out);
}